// round 11
// baseline (speedup 1.0000x reference)
#include <cuda_runtime.h>
#include <cuda_fp16.h>
#include <math.h>
#include <stdint.h>

#define NN   4096
#define DIN  3000
#define DHID 512
#define DOUT 64

// ---------------- scratch (device globals; no runtime allocation) ----------------
__device__ __half g_Xh    [(size_t)NN * DIN];
__device__ __half g_W1h   [(size_t)DIN * DHID];
__device__ __half g_W2h   [(size_t)DHID * DOUT];
__device__ __half g_Wd1h  [(size_t)DOUT * DHID];
__device__ __half g_Wd2h  [(size_t)DHID * DIN];
__device__ __half g_att2h [(size_t)2 * NN * NN];
__device__ __half g_wh1h  [(size_t)NN * DHID];
__device__ __half g_h1h2  [(size_t)2 * NN * DHID];
__device__ __half g_whd1h [(size_t)NN * DHID];
__device__ __half g_wh2h2 [(size_t)2 * NN * DOUT];
__device__ __half g_bigh  [(size_t)NN * DIN];
__device__ __half g_reconh[(size_t)NN * DIN];
__device__ __half g_lath  [(size_t)NN * DOUT];
__device__ uint32_t g_adjPF[(size_t)NN * (NN / 32)];
__device__ uint32_t g_adjPS[(size_t)NN * (NN / 32)];
__device__ float g_embFS[2 * NN * DOUT];
__device__ float g_s   [8 * NN];
__device__ float g_part[(size_t)2 * NN * DHID];

__device__ __forceinline__ uint32_t smem_u32(const void* p) {
    uint32_t a;
    asm("{ .reg .u64 t; cvta.to.shared.u64 t, %1; cvt.u32.u64 %0, t; }" : "=r"(a) : "l"(p));
    return a;
}

#define BK 64
#define STG 3
// Padded strides: conflict-free for ldmatrix (bank offset 4 per row) with LINEAR
// addressing (no XOR swizzle -> no IMAD/LOP3 chains per fragment).
#define A_RSTRIDE 144              // 128B row + 16B pad
#define A_STAGE  (128 * A_RSTRIDE) // 18432
#define B_RSTRIDE2 272             // 256B row + 16B pad (BN=128)
#define B_STAGE2 (64 * B_RSTRIDE2) // 17408
#define SMEM2 (STG * (A_STAGE + B_STAGE2))
#define B_RSTRIDE64 144            // 128B row + 16B pad (BN=64)
#define B_STAGE64 (64 * B_RSTRIDE64)
#define SMEM64 (STG * (A_STAGE + B_STAGE64))

// ============== hgemm: BN=128, 8 warps, 32x64 warp tiles =========================
__global__ void __launch_bounds__(256, 2)
hgemm(const __half* __restrict__ A, const __half* __restrict__ B,
      float* __restrict__ Cf, __half* __restrict__ Ch,
      int M, int N, int K, int epi)
{
    extern __shared__ char smem[];
    const uint32_t sA = smem_u32(smem);
    const uint32_t sB = sA + STG * A_STAGE;

    const int tid = threadIdx.x;
    const int wid = tid >> 5;
    const int lane = tid & 31;
    const int g  = lane >> 2;
    const int tg = lane & 3;
    const int wm = wid & 3;
    const int wn = wid >> 2;

    const int m0 = blockIdx.y * 128;
    const int n0 = blockIdx.x * 128;
    const int gz = gridDim.z;
    const int kChunkR = (((K + gz - 1) / gz) + 63) & ~63;
    const int kBeg = blockIdx.z * kChunkR;
    const int kEnd = min(kBeg + kChunkR, K);
    if (Cf) Cf += (size_t)blockIdx.z * ((size_t)M * N);
    const int T = (kEnd > kBeg) ? ((kEnd - kBeg + BK - 1) / BK) : 0;

    auto loadTile = [&](int kt, int slot) {
        const int k0 = kBeg + kt * BK;
#pragma unroll
        for (int i = 0; i < 4; i++) {
            const int id = tid + 256 * i;
            const int r = id >> 3, c = id & 7;
            const __half* src = A + (size_t)(m0 + r) * K + k0 + c * 8;
            int sz = (k0 + c * 8 < kEnd) ? 16 : 0;
            if (!sz) src = A;
            uint32_t dst = sA + slot * A_STAGE + r * A_RSTRIDE + c * 16;
            asm volatile("cp.async.cg.shared.global [%0], [%1], 16, %2;"
                         :: "r"(dst), "l"(src), "r"(sz));
        }
#pragma unroll
        for (int i = 0; i < 4; i++) {
            const int id = tid + 256 * i;
            const int r = id >> 4, c = id & 15;
            const __half* src = B + (size_t)(k0 + r) * N + n0 + c * 8;
            int sz = ((k0 + r < kEnd) && (n0 + c * 8 < N)) ? 16 : 0;
            if (!sz) src = B;
            uint32_t dst = sB + slot * B_STAGE2 + r * B_RSTRIDE2 + c * 16;
            asm volatile("cp.async.cg.shared.global [%0], [%1], 16, %2;"
                         :: "r"(dst), "l"(src), "r"(sz));
        }
    };

    float acc[2][8][4];
#pragma unroll
    for (int mf = 0; mf < 2; mf++)
#pragma unroll
        for (int nf = 0; nf < 8; nf++)
#pragma unroll
            for (int r = 0; r < 4; r++) acc[mf][nf][r] = 0.f;

    // loop-invariant fragment address offsets (linear addressing)
    const uint32_t aOff0 = (wm * 32 + (lane & 15)) * A_RSTRIDE + (lane >> 4) * 16;
    const uint32_t aOff1 = aOff0 + 16 * A_RSTRIDE;
    const uint32_t bOffBase = (lane & 15) * B_RSTRIDE2 + (wn * 8 + (lane >> 4)) * 16;

#pragma unroll
    for (int s = 0; s < STG - 1; s++) {
        if (s < T) loadTile(s, s);
        asm volatile("cp.async.commit_group;");
    }

    for (int kt = 0; kt < T; kt++) {
        asm volatile("cp.async.wait_group %0;" :: "n"(STG - 2));
        __syncthreads();
        if (kt + STG - 1 < T) loadTile(kt + STG - 1, (kt + STG - 1) % STG);
        asm volatile("cp.async.commit_group;");

        const int slot = kt % STG;
        const uint32_t baseA = sA + slot * A_STAGE;
        const uint32_t baseB = sB + slot * B_STAGE2;
#pragma unroll
        for (int ks = 0; ks < 4; ks++) {
            uint32_t af[2][4];
            {
                const uint32_t a0 = baseA + aOff0 + ks * 32;
                asm volatile("ldmatrix.sync.aligned.m8n8.x4.shared.b16 {%0,%1,%2,%3}, [%4];"
                             : "=r"(af[0][0]), "=r"(af[0][1]),
                               "=r"(af[0][2]), "=r"(af[0][3]) : "r"(a0));
                const uint32_t a1 = baseA + aOff1 + ks * 32;
                asm volatile("ldmatrix.sync.aligned.m8n8.x4.shared.b16 {%0,%1,%2,%3}, [%4];"
                             : "=r"(af[1][0]), "=r"(af[1][1]),
                               "=r"(af[1][2]), "=r"(af[1][3]) : "r"(a1));
            }
            uint32_t bf[8][2];
#pragma unroll
            for (int p = 0; p < 4; p++) {
                const uint32_t addr = baseB + bOffBase + ks * (16 * B_RSTRIDE2) + p * 32;
                uint32_t r0, r1, r2, r3;
                asm volatile("ldmatrix.sync.aligned.m8n8.x4.trans.shared.b16 {%0,%1,%2,%3}, [%4];"
                             : "=r"(r0), "=r"(r1), "=r"(r2), "=r"(r3) : "r"(addr));
                bf[p * 2][0] = r0; bf[p * 2][1] = r1;
                bf[p * 2 + 1][0] = r2; bf[p * 2 + 1][1] = r3;
            }
#pragma unroll
            for (int mf = 0; mf < 2; mf++)
#pragma unroll
                for (int nf = 0; nf < 8; nf++) {
                    asm volatile(
                        "mma.sync.aligned.m16n8k16.row.col.f32.f16.f16.f32 "
                        "{%0,%1,%2,%3}, {%4,%5,%6,%7}, {%8,%9}, {%0,%1,%2,%3};"
                        : "+f"(acc[mf][nf][0]), "+f"(acc[mf][nf][1]),
                          "+f"(acc[mf][nf][2]), "+f"(acc[mf][nf][3])
                        : "r"(af[mf][0]), "r"(af[mf][1]), "r"(af[mf][2]), "r"(af[mf][3]),
                          "r"(bf[nf][0]), "r"(bf[nf][1]));
                }
        }
    }

#pragma unroll
    for (int mf = 0; mf < 2; mf++) {
        const int r0 = m0 + wm * 32 + mf * 16 + g;
#pragma unroll
        for (int nf = 0; nf < 8; nf++) {
            const int c = n0 + wn * 64 + nf * 8 + 2 * tg;
            if (c < N) {
                float v0 = acc[mf][nf][0], v1 = acc[mf][nf][1];
                float v2 = acc[mf][nf][2], v3 = acc[mf][nf][3];
                if (epi) {
                    v0 = (v0 > 0.f) ? v0 : expm1f(v0);
                    v1 = (v1 > 0.f) ? v1 : expm1f(v1);
                    v2 = (v2 > 0.f) ? v2 : expm1f(v2);
                    v3 = (v3 > 0.f) ? v3 : expm1f(v3);
                }
                if (Cf) {
                    *(float2*)&Cf[(size_t)r0 * N + c]       = make_float2(v0, v1);
                    *(float2*)&Cf[(size_t)(r0 + 8) * N + c] = make_float2(v2, v3);
                }
                if (Ch) {
                    *(__half2*)&Ch[(size_t)r0 * N + c]       = __floats2half2_rn(v0, v1);
                    *(__half2*)&Ch[(size_t)(r0 + 8) * N + c] = __floats2half2_rn(v2, v3);
                }
            }
        }
    }
}

// ============== hgemm64: BN=64, dual-B (per-view) support ========================
__global__ void __launch_bounds__(256, 2)
hgemm64(const __half* __restrict__ A, const __half* __restrict__ B,
        const __half* __restrict__ B2,
        float* __restrict__ Cf, __half* __restrict__ Ch,
        int M, int N, int K, int epi)
{
    constexpr int NF = 4;
    extern __shared__ char smem[];
    const uint32_t sA = smem_u32(smem);
    const uint32_t sB = sA + STG * A_STAGE;

    const int tid = threadIdx.x;
    const int wid = tid >> 5;
    const int lane = tid & 31;
    const int g  = lane >> 2;
    const int tg = lane & 3;
    const int wm = wid & 3;
    const int wn = wid >> 2;

    const int m0 = blockIdx.y * 128;
    const __half* Bsel = (2 * m0 >= M) ? B2 : B;
    const int gz = gridDim.z;
    const int kChunkR = (((K + gz - 1) / gz) + 63) & ~63;
    const int kBeg = blockIdx.z * kChunkR;
    const int kEnd = min(kBeg + kChunkR, K);
    if (Cf) Cf += (size_t)blockIdx.z * ((size_t)M * N);
    const int T = (kEnd > kBeg) ? ((kEnd - kBeg + BK - 1) / BK) : 0;

    auto loadTile = [&](int kt, int slot) {
        const int k0 = kBeg + kt * BK;
#pragma unroll
        for (int i = 0; i < 4; i++) {
            const int id = tid + 256 * i;
            const int r = id >> 3, c = id & 7;
            const __half* src = A + (size_t)(m0 + r) * K + k0 + c * 8;
            int sz = (k0 + c * 8 < kEnd) ? 16 : 0;
            if (!sz) src = A;
            uint32_t dst = sA + slot * A_STAGE + r * A_RSTRIDE + c * 16;
            asm volatile("cp.async.cg.shared.global [%0], [%1], 16, %2;"
                         :: "r"(dst), "l"(src), "r"(sz));
        }
#pragma unroll
        for (int i = 0; i < 2; i++) {
            const int id = tid + 256 * i;
            const int r = id >> 3, c = id & 7;
            const __half* src = Bsel + (size_t)(k0 + r) * N + c * 8;
            int sz = ((k0 + r < kEnd) && (c * 8 < N)) ? 16 : 0;
            if (!sz) src = Bsel;
            uint32_t dst = sB + slot * B_STAGE64 + r * B_RSTRIDE64 + c * 16;
            asm volatile("cp.async.cg.shared.global [%0], [%1], 16, %2;"
                         :: "r"(dst), "l"(src), "r"(sz));
        }
    };

    float acc[2][NF][4];
#pragma unroll
    for (int mf = 0; mf < 2; mf++)
#pragma unroll
        for (int nf = 0; nf < NF; nf++)
#pragma unroll
            for (int r = 0; r < 4; r++) acc[mf][nf][r] = 0.f;

    const uint32_t aOff0 = (wm * 32 + (lane & 15)) * A_RSTRIDE + (lane >> 4) * 16;
    const uint32_t aOff1 = aOff0 + 16 * A_RSTRIDE;
    const uint32_t bOffBase = (lane & 15) * B_RSTRIDE64 + (wn * NF + (lane >> 4)) * 16;

#pragma unroll
    for (int s = 0; s < STG - 1; s++) {
        if (s < T) loadTile(s, s);
        asm volatile("cp.async.commit_group;");
    }

    for (int kt = 0; kt < T; kt++) {
        asm volatile("cp.async.wait_group %0;" :: "n"(STG - 2));
        __syncthreads();
        if (kt + STG - 1 < T) loadTile(kt + STG - 1, (kt + STG - 1) % STG);
        asm volatile("cp.async.commit_group;");

        const int slot = kt % STG;
        const uint32_t baseA = sA + slot * A_STAGE;
        const uint32_t baseB = sB + slot * B_STAGE64;
#pragma unroll
        for (int ks = 0; ks < 4; ks++) {
            uint32_t af[2][4];
            {
                const uint32_t a0 = baseA + aOff0 + ks * 32;
                asm volatile("ldmatrix.sync.aligned.m8n8.x4.shared.b16 {%0,%1,%2,%3}, [%4];"
                             : "=r"(af[0][0]), "=r"(af[0][1]),
                               "=r"(af[0][2]), "=r"(af[0][3]) : "r"(a0));
                const uint32_t a1 = baseA + aOff1 + ks * 32;
                asm volatile("ldmatrix.sync.aligned.m8n8.x4.shared.b16 {%0,%1,%2,%3}, [%4];"
                             : "=r"(af[1][0]), "=r"(af[1][1]),
                               "=r"(af[1][2]), "=r"(af[1][3]) : "r"(a1));
            }
            uint32_t bf[NF][2];
#pragma unroll
            for (int p = 0; p < NF / 2; p++) {
                const uint32_t addr = baseB + bOffBase + ks * (16 * B_RSTRIDE64) + p * 32;
                uint32_t r0, r1, r2, r3;
                asm volatile("ldmatrix.sync.aligned.m8n8.x4.trans.shared.b16 {%0,%1,%2,%3}, [%4];"
                             : "=r"(r0), "=r"(r1), "=r"(r2), "=r"(r3) : "r"(addr));
                bf[p * 2][0] = r0; bf[p * 2][1] = r1;
                bf[p * 2 + 1][0] = r2; bf[p * 2 + 1][1] = r3;
            }
#pragma unroll
            for (int mf = 0; mf < 2; mf++)
#pragma unroll
                for (int nf = 0; nf < NF; nf++) {
                    asm volatile(
                        "mma.sync.aligned.m16n8k16.row.col.f32.f16.f16.f32 "
                        "{%0,%1,%2,%3}, {%4,%5,%6,%7}, {%8,%9}, {%0,%1,%2,%3};"
                        : "+f"(acc[mf][nf][0]), "+f"(acc[mf][nf][1]),
                          "+f"(acc[mf][nf][2]), "+f"(acc[mf][nf][3])
                        : "r"(af[mf][0]), "r"(af[mf][1]), "r"(af[mf][2]), "r"(af[mf][3]),
                          "r"(bf[nf][0]), "r"(bf[nf][1]));
                }
        }
    }

#pragma unroll
    for (int mf = 0; mf < 2; mf++) {
        const int r0 = m0 + wm * 32 + mf * 16 + g;
#pragma unroll
        for (int nf = 0; nf < NF; nf++) {
            const int c = wn * (NF * 8) + nf * 8 + 2 * tg;
            if (c < N) {
                float v0 = acc[mf][nf][0], v1 = acc[mf][nf][1];
                float v2 = acc[mf][nf][2], v3 = acc[mf][nf][3];
                if (epi) {
                    v0 = (v0 > 0.f) ? v0 : expm1f(v0);
                    v1 = (v1 > 0.f) ? v1 : expm1f(v1);
                    v2 = (v2 > 0.f) ? v2 : expm1f(v2);
                    v3 = (v3 > 0.f) ? v3 : expm1f(v3);
                }
                if (Cf) {
                    *(float2*)&Cf[(size_t)r0 * N + c]       = make_float2(v0, v1);
                    *(float2*)&Cf[(size_t)(r0 + 8) * N + c] = make_float2(v2, v3);
                }
                if (Ch) {
                    *(__half2*)&Ch[(size_t)r0 * N + c]       = __floats2half2_rn(v0, v1);
                    *(__half2*)&Ch[(size_t)(r0 + 8) * N + c] = __floats2half2_rn(v2, v3);
                }
            }
        }
    }
}

// ---------------- conversions (split so launch #4 is the first GEMM) --------------
#define N4_X   (NN * DIN / 4)
#define N4_W1  (DIN * DHID / 4)
#define N4_W2  (DHID * DOUT / 4)
#define N4_WD1 (DOUT * DHID / 4)
#define N4_WD2 (DHID * DIN / 4)
#define N4_W_TOT (N4_W1 + N4_W2 + N4_WD1 + N4_WD2)

__global__ void conv_X(const float4* __restrict__ X, __half* __restrict__ oX)
{
    int i = blockIdx.x * 256 + threadIdx.x;
    if (i >= N4_X) return;
    float4 v = X[i];
    *(__half2*)&oX[i * 4]     = __floats2half2_rn(v.x, v.y);
    *(__half2*)&oX[i * 4 + 2] = __floats2half2_rn(v.z, v.w);
}

__global__ void conv_W(const float4* __restrict__ W1, const float4* __restrict__ W2,
                       const float4* __restrict__ Wd1, const float4* __restrict__ Wd2,
                       __half* __restrict__ oW1, __half* __restrict__ oW2,
                       __half* __restrict__ oWd1, __half* __restrict__ oWd2)
{
    int i = blockIdx.x * 256 + threadIdx.x;
    if (i >= N4_W_TOT) return;
    const float4* src; __half* dst; int off;
    if (i < N4_W1)                  { src = W1;  dst = oW1;  off = i; }
    else if (i < N4_W1 + N4_W2)     { src = W2;  dst = oW2;  off = i - N4_W1; }
    else if (i < N4_W_TOT - N4_WD2) { src = Wd1; dst = oWd1; off = i - N4_W1 - N4_W2; }
    else                            { src = Wd2; dst = oWd2; off = i - (N4_W_TOT - N4_WD2); }
    float4 v = src[off];
    *(__half2*)&dst[off * 4]     = __floats2half2_rn(v.x, v.y);
    *(__half2*)&dst[off * 4 + 2] = __floats2half2_rn(v.z, v.w);
}

__global__ void pack_both(const int* __restrict__ adjF, const int* __restrict__ adjS,
                          uint32_t* __restrict__ outF, uint32_t* __restrict__ outS, int nwords)
{
    int w = blockIdx.x * 256 + threadIdx.x;
    if (w >= nwords) return;
    const int* p = (blockIdx.y ? adjS : adjF) + (size_t)w * 32;
    uint32_t m = 0;
#pragma unroll
    for (int b = 0; b < 32; b++) m |= (p[b] > 0 ? 1u : 0u) << b;
    (blockIdx.y ? outS : outF)[w] = m;
}

// ---------------- vectorized split-K reduce (elementwise, 2x ILP) -----------------
__global__ void reduce_epi4(const float* __restrict__ part, float* __restrict__ outf,
                            __half* __restrict__ outh, int MN4, int S, int epi)
{
    int t0 = blockIdx.x * 512 + threadIdx.x;
#pragma unroll
    for (int rep = 0; rep < 2; rep++) {
        int t = t0 + rep * 256;
        if (t >= MN4) return;
        float4 v = ((const float4*)part)[t];
        for (int s = 1; s < S; s++) {
            float4 p = ((const float4*)part)[(size_t)s * MN4 + t];
            v.x += p.x; v.y += p.y; v.z += p.z; v.w += p.w;
        }
        if (epi) {
            v.x = (v.x > 0.f) ? v.x : expm1f(v.x);
            v.y = (v.y > 0.f) ? v.y : expm1f(v.y);
            v.z = (v.z > 0.f) ? v.z : expm1f(v.z);
            v.w = (v.w > 0.f) ? v.w : expm1f(v.w);
        }
        if (outf) ((float4*)outf)[t] = v;
        if (outh) {
            __half2 h0 = __floats2half2_rn(v.x, v.y), h1 = __floats2half2_rn(v.z, v.w);
            ((__half2*)outh)[t * 2]     = h0;
            ((__half2*)outh)[t * 2 + 1] = h1;
        }
    }
}

// ---------------- row reduce + GAT scores fused (f = 512, 2 rows/block) -----------
__global__ void reduce_rows_scores512(const float* __restrict__ part, __half* __restrict__ outh,
                                      const float* __restrict__ a,
                                      float* __restrict__ s1, float* __restrict__ s2,
                                      int S, int nrows)
{
    __shared__ float w1[8], w2[8];
    const int tid = threadIdx.x;         // 256
    const int sub = tid >> 7;            // 0,1 -> row within block
    const int lt  = tid & 127;
    const int row = blockIdx.x * 2 + sub;
    const size_t MN = (size_t)nrows * 512;
    const size_t base = (size_t)row * 512 + lt * 4;
    float4 v = *(const float4*)&part[base];
    for (int s = 1; s < S; s++) {
        float4 p = *(const float4*)&part[(size_t)s * MN + base];
        v.x += p.x; v.y += p.y; v.z += p.z; v.w += p.w;
    }
    __half2 h0 = __floats2half2_rn(v.x, v.y), h1 = __floats2half2_rn(v.z, v.w);
    *(__half2*)&outh[base]     = h0;
    *(__half2*)&outh[base + 2] = h1;
    float wv[4] = {__half2float(__low2half(h0)), __half2float(__high2half(h0)),
                   __half2float(__low2half(h1)), __half2float(__high2half(h1))};
    const int c = lt * 4;
    float l1 = 0.f, l2 = 0.f;
#pragma unroll
    for (int j = 0; j < 4; j++) {
        l1 += wv[j] * a[c + j];
        l2 += wv[j] * a[c + j + 512];
    }
#pragma unroll
    for (int o = 16; o; o >>= 1) {
        l1 += __shfl_xor_sync(~0u, l1, o);
        l2 += __shfl_xor_sync(~0u, l2, o);
    }
    if ((tid & 31) == 0) { w1[tid >> 5] = l1; w2[tid >> 5] = l2; }
    __syncthreads();
    if (lt == 0) {
        const int b = sub * 4;
        s1[row] = w1[b] + w1[b + 1] + w1[b + 2] + w1[b + 3];
        s2[row] = w2[b] + w2[b + 1] + w2[b + 2] + w2[b + 3];
    }
}

// ---------------- row reduce + GAT scores fused (f = 64, 4 rows/block) ------------
__global__ void reduce_rows_scores64(const float* __restrict__ part, __half* __restrict__ outh,
                                     const float* __restrict__ a,
                                     float* __restrict__ s1, float* __restrict__ s2,
                                     int S, int nrows)
{
    __shared__ float w1[8], w2[8];
    const int tid = threadIdx.x;         // 256
    const int sub = tid >> 6;            // 0..3 -> row within block
    const int k   = tid & 63;
    const int row = blockIdx.x * 4 + sub;
    const size_t MN = (size_t)nrows * 64;
    float v = part[(size_t)row * 64 + k];
    for (int s = 1; s < S; s++) v += part[(size_t)s * MN + (size_t)row * 64 + k];
    __half h = __float2half_rn(v);
    outh[(size_t)row * 64 + k] = h;
    float wv = __half2float(h);
    float l1 = wv * a[k], l2 = wv * a[k + 64];
#pragma unroll
    for (int o = 16; o; o >>= 1) {
        l1 += __shfl_xor_sync(~0u, l1, o);
        l2 += __shfl_xor_sync(~0u, l2, o);
    }
    if ((tid & 31) == 0) { w1[tid >> 5] = l1; w2[tid >> 5] = l2; }
    __syncthreads();
    if (k == 0) {
        s1[row] = w1[sub * 2] + w1[sub * 2 + 1];
        s2[row] = w2[sub * 2] + w2[sub * 2 + 1];
    }
}

// ---------------- GAT score vectors (generic f % 8 == 0, vectorized) --------------
__global__ void scores_kernel(const __half* __restrict__ WH, int f,
                              const float* __restrict__ a,
                              float* __restrict__ s1, float* __restrict__ s2)
{
    __shared__ float r1s[8], r2s[8];
    const int i = blockIdx.x, tid = threadIdx.x;   // 256
    const __half* row = WH + (size_t)i * f;
    float l1 = 0.f, l2 = 0.f;
    for (int c8 = tid; c8 * 8 < f; c8 += 256) {
        const int c = c8 * 8;
        uint4 u = *(const uint4*)(row + c);
        __half2 h0 = *(__half2*)&u.x, h1 = *(__half2*)&u.y;
        __half2 h2 = *(__half2*)&u.z, h3 = *(__half2*)&u.w;
        float2 f0 = __half22float2(h0), f1 = __half22float2(h1);
        float2 f2 = __half22float2(h2), f3 = __half22float2(h3);
        float wv[8] = {f0.x, f0.y, f1.x, f1.y, f2.x, f2.y, f3.x, f3.y};
#pragma unroll
        for (int j = 0; j < 8; j++) {
            l1 += wv[j] * a[c + j];
            l2 += wv[j] * a[c + f + j];
        }
    }
#pragma unroll
    for (int o = 16; o; o >>= 1) {
        l1 += __shfl_xor_sync(~0u, l1, o);
        l2 += __shfl_xor_sync(~0u, l2, o);
    }
    if ((tid & 31) == 0) { r1s[tid >> 5] = l1; r2s[tid >> 5] = l2; }
    __syncthreads();
    if (tid == 0) {
        float t1 = 0.f, t2 = 0.f;
#pragma unroll
        for (int w = 0; w < 8; w++) { t1 += r1s[w]; t2 += r2s[w]; }
        s1[i] = t1; s2[i] = t2;
    }
}

// ---------------- att row softmax (optionally batched over 2 views) ---------------
__global__ void att_kernel(const float* __restrict__ s1, const float* __restrict__ s2,
                           const uint32_t* __restrict__ adjA, const uint32_t* __restrict__ adjB,
                           __half* __restrict__ att, int per_view)
{
    __shared__ float red[8];
    const int r = blockIdx.x;
    const int i = r & (NN - 1);
    const int view = r >> 12;
    const uint32_t* arow = (view ? adjB : adjA) + (size_t)i * (NN / 32);
    const int vb = per_view ? (view << 12) : 0;
    const float s1i = s1[vb + i];
    const float* s2p = s2 + vb;
    const int tid = threadIdx.x;
    const int base = tid * 16;
    const uint32_t bits = (arow[tid >> 1] >> ((tid & 1) * 16)) & 0xFFFFu;

    float e[16];
    float lmax = -3.4e38f;
#pragma unroll
    for (int u = 0; u < 16; u += 4) {
        float4 s4 = *(const float4*)&s2p[base + u];
        float xs[4] = {s4.x, s4.y, s4.z, s4.w};
#pragma unroll
        for (int q = 0; q < 4; q++) {
            float x = s1i + xs[q];
            x = (x > 0.f) ? x : 0.2f * x;
            float ev = ((bits >> (u + q)) & 1u) ? x : -9e15f;
            e[u + q] = ev;
            lmax = fmaxf(lmax, ev);
        }
    }
#pragma unroll
    for (int o = 16; o; o >>= 1) lmax = fmaxf(lmax, __shfl_xor_sync(~0u, lmax, o));
    if ((tid & 31) == 0) red[tid >> 5] = lmax;
    __syncthreads();
    float m = red[0];
#pragma unroll
    for (int w = 1; w < 8; w++) m = fmaxf(m, red[w]);
    __syncthreads();

    float lsum = 0.f;
#pragma unroll
    for (int u = 0; u < 16; u++) { e[u] = __expf(e[u] - m); lsum += e[u]; }
#pragma unroll
    for (int o = 16; o; o >>= 1) lsum += __shfl_xor_sync(~0u, lsum, o);
    if ((tid & 31) == 0) red[tid >> 5] = lsum;
    __syncthreads();
    float tot = 0.f;
#pragma unroll
    for (int w = 0; w < 8; w++) tot += red[w];
    const float inv = 1.f / tot;

    __half2 h[8];
#pragma unroll
    for (int u = 0; u < 8; u++)
        h[u] = __floats2half2_rn(e[2 * u] * inv, e[2 * u + 1] * inv);
    __half* orow = att + (size_t)r * NN + base;
    *(uint4*)orow       = *(uint4*)&h[0];
    *(uint4*)(orow + 8) = *(uint4*)&h[4];
}

// ---------------- fused attention fusion ------------------------------------------
__global__ void fuse2(const float* __restrict__ e1, const float* __restrict__ e2,
                      const float* __restrict__ w, const float* __restrict__ u,
                      float* __restrict__ fusedf, __half* __restrict__ fusedh,
                      float* __restrict__ alpha)
{
    __shared__ float sh1[64], sh2[64], r1[2], r2[2];
    const int i = blockIdx.x, k = threadIdx.x;      // 64 threads
    sh1[k] = e1[(size_t)i * 64 + k];
    sh2[k] = e2[(size_t)i * 64 + k];
    __syncthreads();
    float a1 = 0.f, a2 = 0.f;
#pragma unroll
    for (int d = 0; d < 64; d++) {
        float wd = w[d * 64 + k];
        a1 += sh1[d] * wd;
        a2 += sh2[d] * wd;
    }
    float uk = u[k];
    float t1 = tanhf(a1) * uk, t2 = tanhf(a2) * uk;
#pragma unroll
    for (int o = 16; o; o >>= 1) {
        t1 += __shfl_xor_sync(~0u, t1, o);
        t2 += __shfl_xor_sync(~0u, t2, o);
    }
    if ((k & 31) == 0) { r1[k >> 5] = t1; r2[k >> 5] = t2; }
    __syncthreads();
    float x0 = r1[0] + r1[1] + 1e-6f;
    float x1 = r2[0] + r2[1] + 1e-6f;
    float m = fmaxf(x0, x1);
    float p0 = expf(x0 - m), p1 = expf(x1 - m);
    float inv = 1.f / (p0 + p1);
    float A0 = p0 * inv, A1 = p1 * inv;
    float v = A0 * sh1[k] + A1 * sh2[k];
    fusedf[(size_t)i * 64 + k] = v;
    if (fusedh) fusedh[(size_t)i * 64 + k] = __float2half_rn(v);
    if (alpha && k < 2) alpha[(size_t)i * 2 + k] = (k == 0) ? A0 : A1;
}

// ---------------- host orchestration ----------------------------------------------
static inline void mm128(const __half* A, const __half* B, float* Cf, __half* Ch,
                         int M, int N, int K, int epi, int splits)
{
    dim3 grid((N + 127) / 128, M / 128, splits);
    hgemm<<<grid, 256, SMEM2>>>(A, B, Cf, Ch, M, N, K, epi);
}
static inline void mm64(const __half* A, const __half* B, const __half* B2,
                        float* Cf, __half* Ch, int M, int K, int epi, int splits)
{
    dim3 grid(1, M / 128, splits);
    hgemm64<<<grid, 256, SMEM64>>>(A, B, B2, Cf, Ch, M, 64, K, epi);
}

extern "C" void kernel_launch(void* const* d_in, const int* in_sizes, int n_in,
                              void* d_out, int out_size)
{
    const float* X       = (const float*)d_in[0];
    const int*   adjF    = (const int*)d_in[1];
    const int*   adjS    = (const int*)d_in[2];
    const float* W_enc1  = (const float*)d_in[3];
    const float* a_enc1  = (const float*)d_in[4];
    const float* W_enc2  = (const float*)d_in[5];
    const float* a_enc2  = (const float*)d_in[6];
    const float* W_dec1  = (const float*)d_in[7];
    const float* a_dec1  = (const float*)d_in[8];
    const float* W_dec2  = (const float*)d_in[9];
    const float* a_dec2  = (const float*)d_in[10];
    const float* w_omega = (const float*)d_in[11];
    const float* u_omega = (const float*)d_in[12];
    (void)in_sizes; (void)n_in; (void)out_size;

    cudaFuncSetAttribute(hgemm, cudaFuncAttributeMaxDynamicSharedMemorySize, SMEM2);
    cudaFuncSetAttribute(hgemm64, cudaFuncAttributeMaxDynamicSharedMemorySize, SMEM64);

    float* out       = (float*)d_out;
    float* out_lat   = out;
    float* out_recon = out + (size_t)NN * DOUT;
    float* out_corr  = out_recon + (size_t)NN * DIN;
    float* out_alpha = out_corr + (size_t)NN * DOUT;

    __half *Xh, *W1h, *W2h, *Wd1h, *Wd2h, *att2, *wh1h, *h1h2, *whd1h, *wh2h2;
    __half *bigh, *reconh, *lath;
    uint32_t *adjPF, *adjPS;
    float *embFS, *sbuf, *part;
    cudaGetSymbolAddress((void**)&Xh,    g_Xh);
    cudaGetSymbolAddress((void**)&W1h,   g_W1h);
    cudaGetSymbolAddress((void**)&W2h,   g_W2h);
    cudaGetSymbolAddress((void**)&Wd1h,  g_Wd1h);
    cudaGetSymbolAddress((void**)&Wd2h,  g_Wd2h);
    cudaGetSymbolAddress((void**)&att2,  g_att2h);
    cudaGetSymbolAddress((void**)&wh1h,  g_wh1h);
    cudaGetSymbolAddress((void**)&h1h2,  g_h1h2);
    cudaGetSymbolAddress((void**)&whd1h, g_whd1h);
    cudaGetSymbolAddress((void**)&wh2h2, g_wh2h2);
    cudaGetSymbolAddress((void**)&bigh,  g_bigh);
    cudaGetSymbolAddress((void**)&reconh,g_reconh);
    cudaGetSymbolAddress((void**)&lath,  g_lath);
    cudaGetSymbolAddress((void**)&adjPF, g_adjPF);
    cudaGetSymbolAddress((void**)&adjPS, g_adjPS);
    cudaGetSymbolAddress((void**)&embFS, g_embFS);
    cudaGetSymbolAddress((void**)&sbuf,  g_s);
    cudaGetSymbolAddress((void**)&part,  g_part);

    float* embF = embFS;
    float* embS = embFS + NN * DOUT;
    float* sA1 = sbuf;              float* sB1 = sbuf + NN;
    float* sA2 = sbuf + 2 * NN;     float* sB2 = sbuf + 4 * NN;

    // ===== one-time conversions (3 launches; puts first GEMM at launch #4) =====
    conv_X<<<(N4_X + 255) / 256, 256>>>((const float4*)X, Xh);
    conv_W<<<(N4_W_TOT + 255) / 256, 256>>>(
        (const float4*)W_enc1, (const float4*)W_enc2,
        (const float4*)W_dec1, (const float4*)W_dec2,
        W1h, W2h, Wd1h, Wd2h);
    pack_both<<<dim3((NN * NN / 32 + 255) / 256, 2), 256>>>(adjF, adjS, adjPF, adjPS,
                                                            NN * NN / 32);

    auto encode_both = [&](const __half* src, int Ksrc) {
        mm128(src, W1h, part, 0, NN, DHID, Ksrc, 0, 2);                  // WH1 (split 2)
        reduce_rows_scores512<<<NN / 2, 256>>>(part, wh1h, a_enc1, sA1, sB1, 2, NN);
        att_kernel<<<2 * NN, 256>>>(sA1, sB1, adjPF, adjPS, att2, 0);
        mm128(att2, wh1h, 0, h1h2, 2 * NN, DHID, NN, 1, 1);              // elu(att@WH1)
        mm64(h1h2, W2h, W2h, part, 0, 2 * NN, DHID, 0, 4);               // WH2 (split 4)
        reduce_rows_scores64<<<2 * NN / 4, 256>>>(part, wh2h2, a_enc2, sA2, sB2, 4, 2 * NN);
        att_kernel<<<2 * NN, 256>>>(sA2, sB2, adjPF, adjPS, att2, 1);
        mm64(att2, wh2h2, wh2h2 + (size_t)NN * DOUT, part, 0, 2 * NN, NN, 0, 4);
        reduce_epi4<<<(2 * NN * DOUT / 4 + 511) / 512, 256>>>(part, embFS, 0,
                                                              2 * NN * DOUT / 4, 4, 1);
    };

    // ===== encode(features, both views) =====
    encode_both(Xh, DIN);

    // ===== attention fusion -> emb_latent, alpha =====
    fuse2<<<NN, 64>>>(embF, embS, w_omega, u_omega, out_lat, lath, out_alpha);

    // ===== decode (spatial adjacency) -> recon =====
    mm128(lath, Wd1h, 0, whd1h, NN, DHID, DOUT, 0, 1);                   // WHd1
    scores_kernel<<<NN, 256>>>(whd1h, DHID, a_dec1, sA2, sB2);
    att_kernel<<<NN, 256>>>(sA2, sB2, adjPS, adjPS, att2, 0);
    mm128(att2, whd1h, part, 0, NN, DHID, NN, 0, 2);                     // att@WHd1 (split 2)
    reduce_epi4<<<(NN * DHID / 4 + 511) / 512, 256>>>(part, 0, h1h2, NN * DHID / 4, 2, 1);
    mm128(h1h2, Wd2h, 0, bigh, NN, DIN, DHID, 0, 1);                     // WHd2 [4096,3000]
    scores_kernel<<<NN, 256>>>(bigh, DIN, a_dec2, sA2, sB2);
    att_kernel<<<NN, 256>>>(sA2, sB2, adjPS, adjPS, att2, 0);
    mm128(att2, bigh, out_recon, reconh, NN, DIN, NN, 1, 1);             // recon

    // ===== corr = fuse(encode(recon, feat), encode(recon, spatial)) =====
    encode_both(reconh, DIN);
    fuse2<<<NN, 64>>>(embF, embS, w_omega, u_omega, out_corr, (__half*)0, (float*)0);
}

// round 12
// speedup vs baseline: 1.1023x; 1.1023x over previous
#include <cuda_runtime.h>
#include <cuda_fp16.h>
#include <math.h>
#include <stdint.h>

#define NN   4096
#define DIN  3000
#define DHID 512
#define DOUT 64

// ---------------- scratch (device globals; no runtime allocation) ----------------
__device__ __half g_Xh    [(size_t)NN * DIN];
__device__ __half g_W1h   [(size_t)DIN * DHID];
__device__ __half g_W2h   [(size_t)DHID * DOUT];
__device__ __half g_Wd1h  [(size_t)DOUT * DHID];
__device__ __half g_Wd2h  [(size_t)DHID * DIN];
__device__ __half g_att2h [(size_t)2 * NN * NN];
__device__ __half g_wh1h  [(size_t)NN * DHID];
__device__ __half g_h1h2  [(size_t)2 * NN * DHID];
__device__ __half g_whd1h [(size_t)NN * DHID];
__device__ __half g_wh2h2 [(size_t)2 * NN * DOUT];
__device__ __half g_bigh  [(size_t)NN * DIN];
__device__ __half g_reconh[(size_t)NN * DIN];
__device__ __half g_lath  [(size_t)NN * DOUT];
__device__ uint32_t g_adjPF[(size_t)NN * (NN / 32)];
__device__ uint32_t g_adjPS[(size_t)NN * (NN / 32)];
__device__ float g_embFS[2 * NN * DOUT];
__device__ float g_s   [8 * NN];
__device__ float g_part[(size_t)2 * NN * DHID];

__device__ __forceinline__ uint32_t smem_u32(const void* p) {
    uint32_t a;
    asm("{ .reg .u64 t; cvta.to.shared.u64 t, %1; cvt.u32.u64 %0, t; }" : "=r"(a) : "l"(p));
    return a;
}

#define BK 64
#define STG 3
#define A_STAGE 16384

// ============== hgemm: BN=128, 8 warps, 32x64 warp tiles (R9 proven config) ======
#define B_STAGE2 16384
#define SMEM2 (STG * (A_STAGE + B_STAGE2))

__global__ void __launch_bounds__(256, 2)
hgemm(const __half* __restrict__ A, const __half* __restrict__ B,
      float* __restrict__ Cf, __half* __restrict__ Ch,
      int M, int N, int K, int epi)
{
    extern __shared__ char smem[];
    const uint32_t sA = smem_u32(smem);
    const uint32_t sB = sA + STG * A_STAGE;

    const int tid = threadIdx.x;
    const int wid = tid >> 5;
    const int lane = tid & 31;
    const int g  = lane >> 2;
    const int tg = lane & 3;
    const int wm = wid & 3;
    const int wn = wid >> 2;

    const int m0 = blockIdx.y * 128;
    const int n0 = blockIdx.x * 128;
    const int gz = gridDim.z;
    const int kChunkR = (((K + gz - 1) / gz) + 63) & ~63;
    const int kBeg = blockIdx.z * kChunkR;
    const int kEnd = min(kBeg + kChunkR, K);
    if (Cf) Cf += (size_t)blockIdx.z * ((size_t)M * N);
    const int T = (kEnd > kBeg) ? ((kEnd - kBeg + BK - 1) / BK) : 0;

    auto loadTile = [&](int kt, int slot) {
        const int k0 = kBeg + kt * BK;
#pragma unroll
        for (int i = 0; i < 4; i++) {
            const int id = tid + 256 * i;
            const int r = id >> 3, c = id & 7;
            const __half* src = A + (size_t)(m0 + r) * K + k0 + c * 8;
            int sz = (k0 + c * 8 < kEnd) ? 16 : 0;
            if (!sz) src = A;
            uint32_t dst = sA + slot * A_STAGE + r * 128 + ((c ^ (r & 7)) << 4);
            asm volatile("cp.async.cg.shared.global [%0], [%1], 16, %2;"
                         :: "r"(dst), "l"(src), "r"(sz));
        }
#pragma unroll
        for (int i = 0; i < 4; i++) {
            const int id = tid + 256 * i;
            const int r = id >> 4, c = id & 15;
            const __half* src = B + (size_t)(k0 + r) * N + n0 + c * 8;
            int sz = ((k0 + r < kEnd) && (n0 + c * 8 < N)) ? 16 : 0;
            if (!sz) src = B;
            const int swz = (c & ~7) | ((c & 7) ^ (r & 7));
            uint32_t dst = sB + slot * B_STAGE2 + r * 256 + (swz << 4);
            asm volatile("cp.async.cg.shared.global [%0], [%1], 16, %2;"
                         :: "r"(dst), "l"(src), "r"(sz));
        }
    };

    float acc[2][8][4];
#pragma unroll
    for (int mf = 0; mf < 2; mf++)
#pragma unroll
        for (int nf = 0; nf < 8; nf++)
#pragma unroll
            for (int r = 0; r < 4; r++) acc[mf][nf][r] = 0.f;

#pragma unroll
    for (int s = 0; s < STG - 1; s++) {
        if (s < T) loadTile(s, s);
        asm volatile("cp.async.commit_group;");
    }

    for (int kt = 0; kt < T; kt++) {
        asm volatile("cp.async.wait_group %0;" :: "n"(STG - 2));
        __syncthreads();
        if (kt + STG - 1 < T) loadTile(kt + STG - 1, (kt + STG - 1) % STG);
        asm volatile("cp.async.commit_group;");

        const int slot = kt % STG;
        const uint32_t baseA = sA + slot * A_STAGE;
        const uint32_t baseB = sB + slot * B_STAGE2;
#pragma unroll
        for (int ks = 0; ks < 4; ks++) {
            uint32_t af[2][4];
#pragma unroll
            for (int mf = 0; mf < 2; mf++) {
                const int row = wm * 32 + mf * 16 + (lane & 15);
                const int c = ks * 2 + (lane >> 4);
                const uint32_t addr = baseA + row * 128 + ((c ^ (row & 7)) << 4);
                asm volatile("ldmatrix.sync.aligned.m8n8.x4.shared.b16 {%0,%1,%2,%3}, [%4];"
                             : "=r"(af[mf][0]), "=r"(af[mf][1]),
                               "=r"(af[mf][2]), "=r"(af[mf][3]) : "r"(addr));
            }
            // interleave: load one B x4 (2 n-frags) then immediately issue its 4 MMAs
#pragma unroll
            for (int p = 0; p < 4; p++) {
                const int kr = ks * 16 + (lane & 15);
                const int cn = wn * 8 + p * 2 + (lane >> 4);
                const int swz = (cn & ~7) | ((cn & 7) ^ (kr & 7));
                const uint32_t addr = baseB + kr * 256 + (swz << 4);
                uint32_t b0, b1, b2, b3;
                asm volatile("ldmatrix.sync.aligned.m8n8.x4.trans.shared.b16 {%0,%1,%2,%3}, [%4];"
                             : "=r"(b0), "=r"(b1), "=r"(b2), "=r"(b3) : "r"(addr));
#pragma unroll
                for (int mf = 0; mf < 2; mf++) {
                    asm volatile(
                        "mma.sync.aligned.m16n8k16.row.col.f32.f16.f16.f32 "
                        "{%0,%1,%2,%3}, {%4,%5,%6,%7}, {%8,%9}, {%0,%1,%2,%3};"
                        : "+f"(acc[mf][p * 2][0]), "+f"(acc[mf][p * 2][1]),
                          "+f"(acc[mf][p * 2][2]), "+f"(acc[mf][p * 2][3])
                        : "r"(af[mf][0]), "r"(af[mf][1]), "r"(af[mf][2]), "r"(af[mf][3]),
                          "r"(b0), "r"(b1));
                    asm volatile(
                        "mma.sync.aligned.m16n8k16.row.col.f32.f16.f16.f32 "
                        "{%0,%1,%2,%3}, {%4,%5,%6,%7}, {%8,%9}, {%0,%1,%2,%3};"
                        : "+f"(acc[mf][p * 2 + 1][0]), "+f"(acc[mf][p * 2 + 1][1]),
                          "+f"(acc[mf][p * 2 + 1][2]), "+f"(acc[mf][p * 2 + 1][3])
                        : "r"(af[mf][0]), "r"(af[mf][1]), "r"(af[mf][2]), "r"(af[mf][3]),
                          "r"(b2), "r"(b3));
                }
            }
        }
    }

#pragma unroll
    for (int mf = 0; mf < 2; mf++) {
        const int r0 = m0 + wm * 32 + mf * 16 + g;
#pragma unroll
        for (int nf = 0; nf < 8; nf++) {
            const int c = n0 + wn * 64 + nf * 8 + 2 * tg;
            if (c < N) {
                float v0 = acc[mf][nf][0], v1 = acc[mf][nf][1];
                float v2 = acc[mf][nf][2], v3 = acc[mf][nf][3];
                if (epi) {
                    v0 = (v0 > 0.f) ? v0 : expm1f(v0);
                    v1 = (v1 > 0.f) ? v1 : expm1f(v1);
                    v2 = (v2 > 0.f) ? v2 : expm1f(v2);
                    v3 = (v3 > 0.f) ? v3 : expm1f(v3);
                }
                if (Cf) {
                    *(float2*)&Cf[(size_t)r0 * N + c]       = make_float2(v0, v1);
                    *(float2*)&Cf[(size_t)(r0 + 8) * N + c] = make_float2(v2, v3);
                }
                if (Ch) {
                    *(__half2*)&Ch[(size_t)r0 * N + c]       = __floats2half2_rn(v0, v1);
                    *(__half2*)&Ch[(size_t)(r0 + 8) * N + c] = __floats2half2_rn(v2, v3);
                }
            }
        }
    }
}

// ============== hgemm64: BN=64, dual-B (per-view) support ========================
#define B_STAGE64 (64 * 64 * 2)
#define SMEM64 (STG * (A_STAGE + B_STAGE64))

__global__ void __launch_bounds__(256, 2)
hgemm64(const __half* __restrict__ A, const __half* __restrict__ B,
        const __half* __restrict__ B2,
        float* __restrict__ Cf, __half* __restrict__ Ch,
        int M, int N, int K, int epi)
{
    constexpr int CH = 8;
    constexpr int NF = 4;
    extern __shared__ char smem[];
    const uint32_t sA = smem_u32(smem);
    const uint32_t sB = sA + STG * A_STAGE;

    const int tid = threadIdx.x;
    const int wid = tid >> 5;
    const int lane = tid & 31;
    const int g  = lane >> 2;
    const int tg = lane & 3;
    const int wm = wid & 3;
    const int wn = wid >> 2;

    const int m0 = blockIdx.y * 128;
    const __half* Bsel = (2 * m0 >= M) ? B2 : B;
    const int gz = gridDim.z;
    const int kChunkR = (((K + gz - 1) / gz) + 63) & ~63;
    const int kBeg = blockIdx.z * kChunkR;
    const int kEnd = min(kBeg + kChunkR, K);
    if (Cf) Cf += (size_t)blockIdx.z * ((size_t)M * N);
    const int T = (kEnd > kBeg) ? ((kEnd - kBeg + BK - 1) / BK) : 0;

    auto loadTile = [&](int kt, int slot) {
        const int k0 = kBeg + kt * BK;
#pragma unroll
        for (int i = 0; i < 4; i++) {
            const int id = tid + 256 * i;
            const int r = id >> 3, c = id & 7;
            const __half* src = A + (size_t)(m0 + r) * K + k0 + c * 8;
            int sz = (k0 + c * 8 < kEnd) ? 16 : 0;
            if (!sz) src = A;
            uint32_t dst = sA + slot * A_STAGE + r * 128 + ((c ^ (r & 7)) << 4);
            asm volatile("cp.async.cg.shared.global [%0], [%1], 16, %2;"
                         :: "r"(dst), "l"(src), "r"(sz));
        }
#pragma unroll
        for (int i = 0; i < 2; i++) {
            const int id = tid + 256 * i;
            const int r = id / CH, c = id % CH;
            const __half* src = Bsel + (size_t)(k0 + r) * N + c * 8;
            int sz = ((k0 + r < kEnd) && (c * 8 < N)) ? 16 : 0;
            if (!sz) src = Bsel;
            const int swz = (c & ~7) | ((c & 7) ^ (r & 7));
            uint32_t dst = sB + slot * B_STAGE64 + r * (CH * 16) + (swz << 4);
            asm volatile("cp.async.cg.shared.global [%0], [%1], 16, %2;"
                         :: "r"(dst), "l"(src), "r"(sz));
        }
    };

    float acc[2][NF][4];
#pragma unroll
    for (int mf = 0; mf < 2; mf++)
#pragma unroll
        for (int nf = 0; nf < NF; nf++)
#pragma unroll
            for (int r = 0; r < 4; r++) acc[mf][nf][r] = 0.f;

#pragma unroll
    for (int s = 0; s < STG - 1; s++) {
        if (s < T) loadTile(s, s);
        asm volatile("cp.async.commit_group;");
    }

    for (int kt = 0; kt < T; kt++) {
        asm volatile("cp.async.wait_group %0;" :: "n"(STG - 2));
        __syncthreads();
        if (kt + STG - 1 < T) loadTile(kt + STG - 1, (kt + STG - 1) % STG);
        asm volatile("cp.async.commit_group;");

        const int slot = kt % STG;
        const uint32_t baseA = sA + slot * A_STAGE;
        const uint32_t baseB = sB + slot * B_STAGE64;
#pragma unroll
        for (int ks = 0; ks < 4; ks++) {
            uint32_t af[2][4];
#pragma unroll
            for (int mf = 0; mf < 2; mf++) {
                const int row = wm * 32 + mf * 16 + (lane & 15);
                const int c = ks * 2 + (lane >> 4);
                const uint32_t addr = baseA + row * 128 + ((c ^ (row & 7)) << 4);
                asm volatile("ldmatrix.sync.aligned.m8n8.x4.shared.b16 {%0,%1,%2,%3}, [%4];"
                             : "=r"(af[mf][0]), "=r"(af[mf][1]),
                               "=r"(af[mf][2]), "=r"(af[mf][3]) : "r"(addr));
            }
#pragma unroll
            for (int p = 0; p < NF / 2; p++) {
                const int kr = ks * 16 + (lane & 15);
                const int cn = wn * NF + p * 2 + (lane >> 4);
                const int swz = (cn & ~7) | ((cn & 7) ^ (kr & 7));
                const uint32_t addr = baseB + kr * (CH * 16) + (swz << 4);
                uint32_t b0, b1, b2, b3;
                asm volatile("ldmatrix.sync.aligned.m8n8.x4.trans.shared.b16 {%0,%1,%2,%3}, [%4];"
                             : "=r"(b0), "=r"(b1), "=r"(b2), "=r"(b3) : "r"(addr));
#pragma unroll
                for (int mf = 0; mf < 2; mf++) {
                    asm volatile(
                        "mma.sync.aligned.m16n8k16.row.col.f32.f16.f16.f32 "
                        "{%0,%1,%2,%3}, {%4,%5,%6,%7}, {%8,%9}, {%0,%1,%2,%3};"
                        : "+f"(acc[mf][p * 2][0]), "+f"(acc[mf][p * 2][1]),
                          "+f"(acc[mf][p * 2][2]), "+f"(acc[mf][p * 2][3])
                        : "r"(af[mf][0]), "r"(af[mf][1]), "r"(af[mf][2]), "r"(af[mf][3]),
                          "r"(b0), "r"(b1));
                    asm volatile(
                        "mma.sync.aligned.m16n8k16.row.col.f32.f16.f16.f32 "
                        "{%0,%1,%2,%3}, {%4,%5,%6,%7}, {%8,%9}, {%0,%1,%2,%3};"
                        : "+f"(acc[mf][p * 2 + 1][0]), "+f"(acc[mf][p * 2 + 1][1]),
                          "+f"(acc[mf][p * 2 + 1][2]), "+f"(acc[mf][p * 2 + 1][3])
                        : "r"(af[mf][0]), "r"(af[mf][1]), "r"(af[mf][2]), "r"(af[mf][3]),
                          "r"(b2), "r"(b3));
                }
            }
        }
    }

#pragma unroll
    for (int mf = 0; mf < 2; mf++) {
        const int r0 = m0 + wm * 32 + mf * 16 + g;
#pragma unroll
        for (int nf = 0; nf < NF; nf++) {
            const int c = wn * (NF * 8) + nf * 8 + 2 * tg;
            if (c < N) {
                float v0 = acc[mf][nf][0], v1 = acc[mf][nf][1];
                float v2 = acc[mf][nf][2], v3 = acc[mf][nf][3];
                if (epi) {
                    v0 = (v0 > 0.f) ? v0 : expm1f(v0);
                    v1 = (v1 > 0.f) ? v1 : expm1f(v1);
                    v2 = (v2 > 0.f) ? v2 : expm1f(v2);
                    v3 = (v3 > 0.f) ? v3 : expm1f(v3);
                }
                if (Cf) {
                    *(float2*)&Cf[(size_t)r0 * N + c]       = make_float2(v0, v1);
                    *(float2*)&Cf[(size_t)(r0 + 8) * N + c] = make_float2(v2, v3);
                }
                if (Ch) {
                    *(__half2*)&Ch[(size_t)r0 * N + c]       = __floats2half2_rn(v0, v1);
                    *(__half2*)&Ch[(size_t)(r0 + 8) * N + c] = __floats2half2_rn(v2, v3);
                }
            }
        }
    }
}

// ---------------- fused one-shot conversions (single launch) ----------------------
#define N4_X   (NN * DIN / 4)
#define N4_W1  (DIN * DHID / 4)
#define N4_W2  (DHID * DOUT / 4)
#define N4_WD1 (DOUT * DHID / 4)
#define N4_WD2 (DHID * DIN / 4)
#define N4_TOT (N4_X + N4_W1 + N4_W2 + N4_WD1 + N4_WD2)

__global__ void conv_all(const float4* __restrict__ X, const float4* __restrict__ W1,
                         const float4* __restrict__ W2, const float4* __restrict__ Wd1,
                         const float4* __restrict__ Wd2,
                         __half* __restrict__ oX, __half* __restrict__ oW1,
                         __half* __restrict__ oW2, __half* __restrict__ oWd1,
                         __half* __restrict__ oWd2)
{
    int i = blockIdx.x * 256 + threadIdx.x;
    if (i >= N4_TOT) return;
    const float4* src; __half* dst; int off;
    if (i < N4_X)                         { src = X;   dst = oX;   off = i; }
    else if (i < N4_X + N4_W1)            { src = W1;  dst = oW1;  off = i - N4_X; }
    else if (i < N4_X + N4_W1 + N4_W2)    { src = W2;  dst = oW2;  off = i - N4_X - N4_W1; }
    else if (i < N4_TOT - N4_WD2)         { src = Wd1; dst = oWd1; off = i - N4_X - N4_W1 - N4_W2; }
    else                                  { src = Wd2; dst = oWd2; off = i - (N4_TOT - N4_WD2); }
    float4 v = src[off];
    *(__half2*)&dst[off * 4]     = __floats2half2_rn(v.x, v.y);
    *(__half2*)&dst[off * 4 + 2] = __floats2half2_rn(v.z, v.w);
}

__global__ void pack_both(const int* __restrict__ adjF, const int* __restrict__ adjS,
                          uint32_t* __restrict__ outF, uint32_t* __restrict__ outS, int nwords)
{
    int w = blockIdx.x * 256 + threadIdx.x;
    if (w >= nwords) return;
    const int* p = (blockIdx.y ? adjS : adjF) + (size_t)w * 32;
    uint32_t m = 0;
#pragma unroll
    for (int b = 0; b < 32; b++) m |= (p[b] > 0 ? 1u : 0u) << b;
    (blockIdx.y ? outS : outF)[w] = m;
}

// ---------------- vectorized split-K reduce (elementwise) -------------------------
__global__ void reduce_epi4(const float* __restrict__ part, float* __restrict__ outf,
                            __half* __restrict__ outh, int MN4, int S, int epi)
{
    int t = blockIdx.x * 256 + threadIdx.x;
    if (t >= MN4) return;
    float4 v = ((const float4*)part)[t];
    for (int s = 1; s < S; s++) {
        float4 p = ((const float4*)part)[(size_t)s * MN4 + t];
        v.x += p.x; v.y += p.y; v.z += p.z; v.w += p.w;
    }
    if (epi) {
        v.x = (v.x > 0.f) ? v.x : expm1f(v.x);
        v.y = (v.y > 0.f) ? v.y : expm1f(v.y);
        v.z = (v.z > 0.f) ? v.z : expm1f(v.z);
        v.w = (v.w > 0.f) ? v.w : expm1f(v.w);
    }
    if (outf) ((float4*)outf)[t] = v;
    if (outh) {
        __half2 h0 = __floats2half2_rn(v.x, v.y), h1 = __floats2half2_rn(v.z, v.w);
        ((__half2*)outh)[t * 2]     = h0;
        ((__half2*)outh)[t * 2 + 1] = h1;
    }
}

// ---------------- row reduce + GAT scores fused (f = 512) -------------------------
__global__ void reduce_rows_scores512(const float* __restrict__ part, __half* __restrict__ outh,
                                      const float* __restrict__ a,
                                      float* __restrict__ s1, float* __restrict__ s2, int S)
{
    __shared__ float w1[4], w2[4];
    const int row = blockIdx.x, tid = threadIdx.x;   // 128 threads
    const size_t MN = (size_t)gridDim.x * 512;
    const size_t base = (size_t)row * 512 + tid * 4;
    float4 v = *(const float4*)&part[base];
    for (int s = 1; s < S; s++) {
        float4 p = *(const float4*)&part[(size_t)s * MN + base];
        v.x += p.x; v.y += p.y; v.z += p.z; v.w += p.w;
    }
    __half2 h0 = __floats2half2_rn(v.x, v.y), h1 = __floats2half2_rn(v.z, v.w);
    *(__half2*)&outh[base]     = h0;
    *(__half2*)&outh[base + 2] = h1;
    float wv[4] = {__half2float(__low2half(h0)), __half2float(__high2half(h0)),
                   __half2float(__low2half(h1)), __half2float(__high2half(h1))};
    const int c = tid * 4;
    float l1 = 0.f, l2 = 0.f;
#pragma unroll
    for (int j = 0; j < 4; j++) {
        l1 += wv[j] * a[c + j];
        l2 += wv[j] * a[c + j + 512];
    }
#pragma unroll
    for (int o = 16; o; o >>= 1) {
        l1 += __shfl_xor_sync(~0u, l1, o);
        l2 += __shfl_xor_sync(~0u, l2, o);
    }
    if ((tid & 31) == 0) { w1[tid >> 5] = l1; w2[tid >> 5] = l2; }
    __syncthreads();
    if (tid == 0) {
        s1[row] = w1[0] + w1[1] + w1[2] + w1[3];
        s2[row] = w2[0] + w2[1] + w2[2] + w2[3];
    }
}

// ---------------- row reduce + GAT scores fused (f = 64) --------------------------
__global__ void reduce_rows_scores64(const float* __restrict__ part, __half* __restrict__ outh,
                                     const float* __restrict__ a,
                                     float* __restrict__ s1, float* __restrict__ s2, int S)
{
    __shared__ float w1[2], w2[2];
    const int row = blockIdx.x, k = threadIdx.x;     // 64 threads
    const size_t MN = (size_t)gridDim.x * 64;
    float v = part[(size_t)row * 64 + k];
    for (int s = 1; s < S; s++) v += part[(size_t)s * MN + (size_t)row * 64 + k];
    __half h = __float2half_rn(v);
    outh[(size_t)row * 64 + k] = h;
    float wv = __half2float(h);
    float l1 = wv * a[k], l2 = wv * a[k + 64];
#pragma unroll
    for (int o = 16; o; o >>= 1) {
        l1 += __shfl_xor_sync(~0u, l1, o);
        l2 += __shfl_xor_sync(~0u, l2, o);
    }
    if ((k & 31) == 0) { w1[k >> 5] = l1; w2[k >> 5] = l2; }
    __syncthreads();
    if (k == 0) { s1[row] = w1[0] + w1[1]; s2[row] = w2[0] + w2[1]; }
}

// ---------------- GAT score vectors (generic f, used in decode) -------------------
__global__ void scores_kernel(const __half* __restrict__ WH, int f,
                              const float* __restrict__ a,
                              float* __restrict__ s1, float* __restrict__ s2)
{
    __shared__ float r1[256], r2[256];
    const int i = blockIdx.x, tid = threadIdx.x;
    const __half* row = WH + (size_t)i * f;
    float l1 = 0.f, l2 = 0.f;
    for (int c = tid; c < f; c += 256) {
        float w = __half2float(row[c]);
        l1 += w * a[c];
        l2 += w * a[c + f];
    }
    r1[tid] = l1; r2[tid] = l2;
    __syncthreads();
    for (int s = 128; s > 0; s >>= 1) {
        if (tid < s) { r1[tid] += r1[tid + s]; r2[tid] += r2[tid + s]; }
        __syncthreads();
    }
    if (tid == 0) { s1[i] = r1[0]; s2[i] = r2[0]; }
}

// ---------------- att row softmax (optionally batched over 2 views) ---------------
__global__ void att_kernel(const float* __restrict__ s1, const float* __restrict__ s2,
                           const uint32_t* __restrict__ adjA, const uint32_t* __restrict__ adjB,
                           __half* __restrict__ att, int per_view)
{
    __shared__ float red[8];
    const int r = blockIdx.x;
    const int i = r & (NN - 1);
    const int view = r >> 12;
    const uint32_t* arow = (view ? adjB : adjA) + (size_t)i * (NN / 32);
    const int vb = per_view ? (view << 12) : 0;
    const float s1i = s1[vb + i];
    const float* s2p = s2 + vb;
    const int tid = threadIdx.x;
    const int base = tid * 16;
    const uint32_t bits = (arow[tid >> 1] >> ((tid & 1) * 16)) & 0xFFFFu;

    float e[16];
    float lmax = -3.4e38f;
#pragma unroll
    for (int u = 0; u < 16; u += 4) {
        float4 s4 = *(const float4*)&s2p[base + u];
        float xs[4] = {s4.x, s4.y, s4.z, s4.w};
#pragma unroll
        for (int q = 0; q < 4; q++) {
            float x = s1i + xs[q];
            x = (x > 0.f) ? x : 0.2f * x;
            float ev = ((bits >> (u + q)) & 1u) ? x : -9e15f;
            e[u + q] = ev;
            lmax = fmaxf(lmax, ev);
        }
    }
#pragma unroll
    for (int o = 16; o; o >>= 1) lmax = fmaxf(lmax, __shfl_xor_sync(~0u, lmax, o));
    if ((tid & 31) == 0) red[tid >> 5] = lmax;
    __syncthreads();
    float m = red[0];
#pragma unroll
    for (int w = 1; w < 8; w++) m = fmaxf(m, red[w]);
    __syncthreads();

    float lsum = 0.f;
#pragma unroll
    for (int u = 0; u < 16; u++) { e[u] = __expf(e[u] - m); lsum += e[u]; }
#pragma unroll
    for (int o = 16; o; o >>= 1) lsum += __shfl_xor_sync(~0u, lsum, o);
    if ((tid & 31) == 0) red[tid >> 5] = lsum;
    __syncthreads();
    float tot = 0.f;
#pragma unroll
    for (int w = 0; w < 8; w++) tot += red[w];
    const float inv = 1.f / tot;

    __half2 h[8];
#pragma unroll
    for (int u = 0; u < 8; u++)
        h[u] = __floats2half2_rn(e[2 * u] * inv, e[2 * u + 1] * inv);
    __half* orow = att + (size_t)r * NN + base;
    *(uint4*)orow       = *(uint4*)&h[0];
    *(uint4*)(orow + 8) = *(uint4*)&h[4];
}

// ---------------- fused attention fusion ------------------------------------------
__global__ void fuse2(const float* __restrict__ e1, const float* __restrict__ e2,
                      const float* __restrict__ w, const float* __restrict__ u,
                      float* __restrict__ fusedf, __half* __restrict__ fusedh,
                      float* __restrict__ alpha)
{
    __shared__ float sh1[64], sh2[64], r1[2], r2[2];
    const int i = blockIdx.x, k = threadIdx.x;      // 64 threads
    sh1[k] = e1[(size_t)i * 64 + k];
    sh2[k] = e2[(size_t)i * 64 + k];
    __syncthreads();
    float a1 = 0.f, a2 = 0.f;
#pragma unroll
    for (int d = 0; d < 64; d++) {
        float wd = w[d * 64 + k];
        a1 += sh1[d] * wd;
        a2 += sh2[d] * wd;
    }
    float uk = u[k];
    float t1 = tanhf(a1) * uk, t2 = tanhf(a2) * uk;
#pragma unroll
    for (int o = 16; o; o >>= 1) {
        t1 += __shfl_xor_sync(~0u, t1, o);
        t2 += __shfl_xor_sync(~0u, t2, o);
    }
    if ((k & 31) == 0) { r1[k >> 5] = t1; r2[k >> 5] = t2; }
    __syncthreads();
    float x0 = r1[0] + r1[1] + 1e-6f;
    float x1 = r2[0] + r2[1] + 1e-6f;
    float m = fmaxf(x0, x1);
    float p0 = expf(x0 - m), p1 = expf(x1 - m);
    float inv = 1.f / (p0 + p1);
    float A0 = p0 * inv, A1 = p1 * inv;
    float v = A0 * sh1[k] + A1 * sh2[k];
    fusedf[(size_t)i * 64 + k] = v;
    if (fusedh) fusedh[(size_t)i * 64 + k] = __float2half_rn(v);
    if (alpha && k < 2) alpha[(size_t)i * 2 + k] = (k == 0) ? A0 : A1;
}

// ---------------- host orchestration ----------------------------------------------
static inline void mm128(const __half* A, const __half* B, float* Cf, __half* Ch,
                         int M, int N, int K, int epi, int splits)
{
    dim3 grid((N + 127) / 128, M / 128, splits);
    hgemm<<<grid, 256, SMEM2>>>(A, B, Cf, Ch, M, N, K, epi);
}
static inline void mm64(const __half* A, const __half* B, const __half* B2,
                        float* Cf, __half* Ch, int M, int K, int epi, int splits)
{
    dim3 grid(1, M / 128, splits);
    hgemm64<<<grid, 256, SMEM64>>>(A, B, B2, Cf, Ch, M, 64, K, epi);
}

extern "C" void kernel_launch(void* const* d_in, const int* in_sizes, int n_in,
                              void* d_out, int out_size)
{
    const float* X       = (const float*)d_in[0];
    const int*   adjF    = (const int*)d_in[1];
    const int*   adjS    = (const int*)d_in[2];
    const float* W_enc1  = (const float*)d_in[3];
    const float* a_enc1  = (const float*)d_in[4];
    const float* W_enc2  = (const float*)d_in[5];
    const float* a_enc2  = (const float*)d_in[6];
    const float* W_dec1  = (const float*)d_in[7];
    const float* a_dec1  = (const float*)d_in[8];
    const float* W_dec2  = (const float*)d_in[9];
    const float* a_dec2  = (const float*)d_in[10];
    const float* w_omega = (const float*)d_in[11];
    const float* u_omega = (const float*)d_in[12];
    (void)in_sizes; (void)n_in; (void)out_size;

    cudaFuncSetAttribute(hgemm, cudaFuncAttributeMaxDynamicSharedMemorySize, SMEM2);
    cudaFuncSetAttribute(hgemm64, cudaFuncAttributeMaxDynamicSharedMemorySize, SMEM64);

    float* out       = (float*)d_out;
    float* out_lat   = out;
    float* out_recon = out + (size_t)NN * DOUT;
    float* out_corr  = out_recon + (size_t)NN * DIN;
    float* out_alpha = out_corr + (size_t)NN * DOUT;

    __half *Xh, *W1h, *W2h, *Wd1h, *Wd2h, *att2, *wh1h, *h1h2, *whd1h, *wh2h2;
    __half *bigh, *reconh, *lath;
    uint32_t *adjPF, *adjPS;
    float *embFS, *sbuf, *part;
    cudaGetSymbolAddress((void**)&Xh,    g_Xh);
    cudaGetSymbolAddress((void**)&W1h,   g_W1h);
    cudaGetSymbolAddress((void**)&W2h,   g_W2h);
    cudaGetSymbolAddress((void**)&Wd1h,  g_Wd1h);
    cudaGetSymbolAddress((void**)&Wd2h,  g_Wd2h);
    cudaGetSymbolAddress((void**)&att2,  g_att2h);
    cudaGetSymbolAddress((void**)&wh1h,  g_wh1h);
    cudaGetSymbolAddress((void**)&h1h2,  g_h1h2);
    cudaGetSymbolAddress((void**)&whd1h, g_whd1h);
    cudaGetSymbolAddress((void**)&wh2h2, g_wh2h2);
    cudaGetSymbolAddress((void**)&bigh,  g_bigh);
    cudaGetSymbolAddress((void**)&reconh,g_reconh);
    cudaGetSymbolAddress((void**)&lath,  g_lath);
    cudaGetSymbolAddress((void**)&adjPF, g_adjPF);
    cudaGetSymbolAddress((void**)&adjPS, g_adjPS);
    cudaGetSymbolAddress((void**)&embFS, g_embFS);
    cudaGetSymbolAddress((void**)&sbuf,  g_s);
    cudaGetSymbolAddress((void**)&part,  g_part);

    float* embF = embFS;
    float* embS = embFS + NN * DOUT;
    float* sA1 = sbuf;              float* sB1 = sbuf + NN;
    float* sA2 = sbuf + 2 * NN;     float* sB2 = sbuf + 4 * NN;

    // ===== one-time conversions (2 launches) =====
    conv_all<<<(N4_TOT + 255) / 256, 256>>>(
        (const float4*)X, (const float4*)W_enc1, (const float4*)W_enc2,
        (const float4*)W_dec1, (const float4*)W_dec2,
        Xh, W1h, W2h, Wd1h, Wd2h);
    pack_both<<<dim3((NN * NN / 32 + 255) / 256, 2), 256>>>(adjF, adjS, adjPF, adjPS,
                                                            NN * NN / 32);

    auto encode_both = [&](const __half* src, int Ksrc) {
        mm128(src, W1h, part, 0, NN, DHID, Ksrc, 0, 2);                  // WH1 (split 2)
        reduce_rows_scores512<<<NN, 128>>>(part, wh1h, a_enc1, sA1, sB1, 2);
        att_kernel<<<2 * NN, 256>>>(sA1, sB1, adjPF, adjPS, att2, 0);
        mm128(att2, wh1h, 0, h1h2, 2 * NN, DHID, NN, 1, 1);              // elu(att@WH1)
        mm64(h1h2, W2h, W2h, part, 0, 2 * NN, DHID, 0, 4);               // WH2 (split 4)
        reduce_rows_scores64<<<2 * NN, 64>>>(part, wh2h2, a_enc2, sA2, sB2, 4);
        att_kernel<<<2 * NN, 256>>>(sA2, sB2, adjPF, adjPS, att2, 1);
        mm64(att2, wh2h2, wh2h2 + (size_t)NN * DOUT, part, 0, 2 * NN, NN, 0, 4);
        reduce_epi4<<<(2 * NN * DOUT / 4 + 255) / 256, 256>>>(part, embFS, 0,
                                                              2 * NN * DOUT / 4, 4, 1);
    };

    // ===== encode(features, both views) =====
    encode_both(Xh, DIN);

    // ===== attention fusion -> emb_latent, alpha =====
    fuse2<<<NN, 64>>>(embF, embS, w_omega, u_omega, out_lat, lath, out_alpha);

    // ===== decode (spatial adjacency) -> recon =====
    mm128(lath, Wd1h, 0, whd1h, NN, DHID, DOUT, 0, 1);                   // WHd1
    scores_kernel<<<NN, 256>>>(whd1h, DHID, a_dec1, sA2, sB2);
    att_kernel<<<NN, 256>>>(sA2, sB2, adjPS, adjPS, att2, 0);
    mm128(att2, whd1h, part, 0, NN, DHID, NN, 0, 2);                     // att@WHd1 (split 2)
    reduce_epi4<<<(NN * DHID / 4 + 255) / 256, 256>>>(part, 0, h1h2, NN * DHID / 4, 2, 1);
    mm128(h1h2, Wd2h, 0, bigh, NN, DIN, DHID, 0, 1);                     // WHd2 [4096,3000]
    scores_kernel<<<NN, 256>>>(bigh, DIN, a_dec2, sA2, sB2);
    att_kernel<<<NN, 256>>>(sA2, sB2, adjPS, adjPS, att2, 0);
    mm128(att2, bigh, out_recon, reconh, NN, DIN, NN, 1, 1);             // recon

    // ===== corr = fuse(encode(recon, feat), encode(recon, spatial)) =====
    encode_both(reconh, DIN);
    fuse2<<<NN, 64>>>(embF, embS, w_omega, u_omega, out_corr, (__half*)0, (float*)0);
}